// round 14
// baseline (speedup 1.0000x reference)
#include <cuda_runtime.h>
#include <math_constants.h>

typedef unsigned long long ull;

// Problem constants
#define NROWS 262144
#define DIMQ  128
#define MFEAT 256
#define SCALE 0.29730177875068026f   // 128^-0.25
#define INV_SQRT_M 0.0625f           // 1/sqrt(256)
#define PHI_EPS 1e-4f

// GEMM tiling: BM=64 rows x BN=256 (full width), 256 threads, warp owns 8 rows,
// lane owns cols [lane*8, lane*8+8). K=128 streamed in 8 chunks of 16.
#define BM 64
#define GEMM_THREADS 256
#define GEMM_BLOCKS (NROWS / BM)            // 4096
#define SX_STRIDE 132                       // 128 + 4 pad (row-major X tile)
#define OM_CHUNK_FLOATS (16 * MFEAT)        // 4096
#define SMEM_FLOATS (BM * SX_STRIDE + 2 * OM_CHUNK_FLOATS)
#define SMEM_BYTES  (SMEM_FLOATS * 4)       // 66560 B -> 2 CTAs/SM

// kp pass
#define KP_BLOCKS 1024
#define KP_ROWS_PER_BLOCK (NROWS / KP_BLOCKS)   // 256

// Scratch (device globals: allocation-free). g_UK holds U'_K then Kp.
__device__ float g_UK[(size_t)NROWS * MFEAT];
__device__ float g_part[KP_BLOCKS * MFEAT];
__device__ float g_ksum[MFEAT];
__device__ unsigned g_kmax_bits;

// Monotonic float<->uint encoding for atomicMax on floats
__device__ __forceinline__ unsigned fenc(float f) {
    unsigned u = __float_as_uint(f);
    return (u >> 31) ? ~u : (u | 0x80000000u);
}
__device__ __forceinline__ float fdec(unsigned u) {
    return (u >> 31) ? __uint_as_float(u & 0x7fffffffu) : __uint_as_float(~u);
}

// Packed fp32x2 FMA (Blackwell FFMA2 — only reachable via PTX)
__device__ __forceinline__ ull fma2(ull a, ull b, ull c) {
    ull d;
    asm("fma.rn.f32x2 %0, %1, %2, %3;" : "=l"(d) : "l"(a), "l"(b), "l"(c));
    return d;
}
__device__ __forceinline__ ull pack2(float lo, float hi) {
    ull r;
    asm("mov.b64 %0, {%1, %2};" : "=l"(r) : "r"(__float_as_uint(lo)), "r"(__float_as_uint(hi)));
    return r;
}
__device__ __forceinline__ void unpack2(ull p, float& lo, float& hi) {
    unsigned a, b;
    asm("mov.b64 {%0, %1}, %2;" : "=r"(a), "=r"(b) : "l"(p));
    lo = __uint_as_float(a);
    hi = __uint_as_float(b);
}

__global__ void init_kernel() { g_kmax_bits = 0u; }

// ---------------------------------------------------------------------------
// Fused GEMM: U = (X*SCALE) @ omega, h folded in.
//  IS_K: store U-h to g_UK, track global max of raw U (atomicMax, deterministic).
// !IS_K: full Q epilogue in-registers: row-max, Qp, w=<Qp,Kp>, nrm=<Qp,ksum>,
//        out = (w/nrm)*V. No U_Q scratch traffic at all.
// ---------------------------------------------------------------------------
template <bool IS_K>
__global__ __launch_bounds__(GEMM_THREADS, 2)
void gemm_kernel(const float* __restrict__ X,
                 const float* __restrict__ omega,
                 const float* __restrict__ V,
                 float* __restrict__ out)
{
    extern __shared__ float smem[];
    float* sX  = smem;                       // [64][132] row-major, scaled
    float* sOm = smem + BM * SX_STRIDE;      // [2][16][256]

    const int tid  = threadIdx.x;
    const int lane = tid & 31;
    const int w    = tid >> 5;               // warp 0..7 -> rows w*8..w*8+7
    const size_t row0 = (size_t)blockIdx.x * BM;

    // Load X tile (scaled), coalesced; 8 float4 per thread.
    {
        const float4* Xg = (const float4*)(X + row0 * DIMQ);
        #pragma unroll
        for (int q = 0; q < 8; q++) {
            int f = tid + q * GEMM_THREADS;  // f4 index: r = f/32, c4 = f%32
            float4 v = Xg[f];
            v.x *= SCALE; v.y *= SCALE; v.z *= SCALE; v.w *= SCALE;
            int r = f >> 5, c4 = f & 31;
            *(float4*)(sX + r * SX_STRIDE + c4 * 4) = v;
        }
    }

    // Prefetch omega chunk 0 into registers (4 float4 / thread)
    float4 pf[4];
    {
        const float4* Og = (const float4*)omega;
        #pragma unroll
        for (int q = 0; q < 4; q++) pf[q] = Og[tid + q * GEMM_THREADS];
    }
    __syncthreads();

    // h per warp row (all lanes end up with h[i]); conflict-free LDS.
    float h[8];
    #pragma unroll
    for (int i = 0; i < 8; i++) {
        const float* xr = sX + (size_t)(w * 8 + i) * SX_STRIDE;
        float s = 0.f;
        #pragma unroll
        for (int c = 0; c < 4; c++) { float v = xr[lane + c * 32]; s = fmaf(v, v, s); }
        #pragma unroll
        for (int o = 16; o > 0; o >>= 1) s += __shfl_xor_sync(0xffffffffu, s, o);
        h[i] = 0.5f * s;
    }

    // Accumulators: acc[i][jp] = (u[row i][lane*8+2jp], u[row i][lane*8+2jp+1])
    ull acc[8][4];
    #pragma unroll
    for (int i = 0; i < 8; i++)
        #pragma unroll
        for (int jp = 0; jp < 4; jp++) acc[i][jp] = 0ull;

    // Mainloop: 8 chunks of BK=16, double-buffered omega.
    #pragma unroll 1
    for (int chunk = 0; chunk < 8; chunk++) {
        float* so = sOm + (chunk & 1) * OM_CHUNK_FLOATS;
        // Commit prefetched chunk to smem (coalesced, conflict-free).
        #pragma unroll
        for (int q = 0; q < 4; q++)
            *(float4*)(so + (size_t)(tid + q * GEMM_THREADS) * 4) = pf[q];
        __syncthreads();

        // Issue next chunk's global loads early (hidden under compute).
        if (chunk < 7) {
            const float4* Og = (const float4*)(omega + (size_t)(chunk + 1) * 16 * MFEAT);
            #pragma unroll
            for (int q = 0; q < 4; q++) pf[q] = Og[tid + q * GEMM_THREADS];
        }

        #pragma unroll
        for (int kk = 0; kk < 16; kk++) {
            const int kg = chunk * 16 + kk;
            const ulonglong2* bq =
                (const ulonglong2*)(so + kk * MFEAT + lane * 8);
            ulonglong2 bA = bq[0], bB = bq[1];
            #pragma unroll
            for (int i = 0; i < 8; i++) {
                float a = sX[(size_t)(w * 8 + i) * SX_STRIDE + kg];  // broadcast LDS
                ull ad = pack2(a, a);
                acc[i][0] = fma2(ad, bA.x, acc[i][0]);
                acc[i][1] = fma2(ad, bA.y, acc[i][1]);
                acc[i][2] = fma2(ad, bB.x, acc[i][2]);
                acc[i][3] = fma2(ad, bB.y, acc[i][3]);
            }
        }
        __syncthreads();
    }

    if (IS_K) {
        // --- K epilogue: store U-h coalesced, track raw-U global max ---
        float umax = -CUDART_INF_F;
        #pragma unroll
        for (int i = 0; i < 8; i++) {
            float u[8];
            #pragma unroll
            for (int jp = 0; jp < 4; jp++) unpack2(acc[i][jp], u[2 * jp], u[2 * jp + 1]);
            #pragma unroll
            for (int j = 0; j < 8; j++) umax = fmaxf(umax, u[j]);
            const float hi_ = h[i];
            const size_t row = row0 + w * 8 + i;
            float4* dst = (float4*)(g_UK + row * MFEAT + lane * 8);
            dst[0] = make_float4(u[0] - hi_, u[1] - hi_, u[2] - hi_, u[3] - hi_);
            dst[1] = make_float4(u[4] - hi_, u[5] - hi_, u[6] - hi_, u[7] - hi_);
        }
        #pragma unroll
        for (int o = 16; o > 0; o >>= 1)
            umax = fmaxf(umax, __shfl_xor_sync(0xffffffffu, umax, o));
        if (lane == 0) atomicMax(&g_kmax_bits, fenc(umax));
    } else {
        // --- Q epilogue: softmax-feature + weighting + output, in-registers ---
        float ks[8];
        {
            const float4* kg = (const float4*)(g_ksum + lane * 8);
            float4 k0 = kg[0], k1 = kg[1];
            ks[0] = k0.x; ks[1] = k0.y; ks[2] = k0.z; ks[3] = k0.w;
            ks[4] = k1.x; ks[5] = k1.y; ks[6] = k1.z; ks[7] = k1.w;
        }
        #pragma unroll
        for (int i = 0; i < 8; i++) {
            float u[8];
            #pragma unroll
            for (int jp = 0; jp < 4; jp++) unpack2(acc[i][jp], u[2 * jp], u[2 * jp + 1]);
            const float hi_ = h[i];
            #pragma unroll
            for (int j = 0; j < 8; j++) u[j] -= hi_;

            float m = u[0];
            #pragma unroll
            for (int j = 1; j < 8; j++) m = fmaxf(m, u[j]);
            #pragma unroll
            for (int o = 16; o > 0; o >>= 1)
                m = fmaxf(m, __shfl_xor_sync(0xffffffffu, m, o));

            const size_t row = row0 + w * 8 + i;
            const float4* kpg = (const float4*)(g_UK + row * MFEAT + lane * 8);
            float4 kp0 = kpg[0], kp1 = kpg[1];
            float kp[8] = { kp0.x, kp0.y, kp0.z, kp0.w, kp1.x, kp1.y, kp1.z, kp1.w };

            float wv = 0.f, nrm = 0.f;
            #pragma unroll
            for (int j = 0; j < 8; j++) {
                float qp = (__expf(u[j] - m) + PHI_EPS) * INV_SQRT_M;
                wv  = fmaf(qp, kp[j], wv);
                nrm = fmaf(qp, ks[j], nrm);
            }
            #pragma unroll
            for (int o = 16; o > 0; o >>= 1) {
                wv  += __shfl_xor_sync(0xffffffffu, wv, o);
                nrm += __shfl_xor_sync(0xffffffffu, nrm, o);
            }
            const float scale = wv / (nrm + 1e-8f);

            const size_t vb = row * DIMQ + lane;
            #pragma unroll
            for (int c = 0; c < 4; c++)
                out[vb + c * 32] = scale * V[vb + c * 32];
        }
    }
}

// ---------------------------------------------------------------------------
// kp: Kp = (exp(U' - gmax) + eps)/sqrt(m), overwrite g_UK, per-block column
// partial sums (deterministic). Already at DRAM roofline (~86us).
// ---------------------------------------------------------------------------
__global__ __launch_bounds__(MFEAT)
void kp_kernel()
{
    const int tid = threadIdx.x;
    const float gmax = fdec(g_kmax_bits);
    const size_t base = (size_t)blockIdx.x * KP_ROWS_PER_BLOCK * MFEAT + tid;

    float psum = 0.f;
    #pragma unroll 4
    for (int r = 0; r < KP_ROWS_PER_BLOCK; r++) {
        size_t idx = base + (size_t)r * MFEAT;
        float u = g_UK[idx];
        float kp = (__expf(u - gmax) + PHI_EPS) * INV_SQRT_M;
        g_UK[idx] = kp;
        psum += kp;
    }
    g_part[blockIdx.x * MFEAT + tid] = psum;
}

// 1 block, 1024 threads: 4 slices x 256 columns, then combine.
__global__ __launch_bounds__(1024)
void ksum_kernel()
{
    __shared__ float red[4][MFEAT];
    const int col = threadIdx.x & (MFEAT - 1);
    const int slice = threadIdx.x >> 8;
    const int per = KP_BLOCKS / 4;

    float s = 0.f;
    #pragma unroll 8
    for (int b = 0; b < per; b++)
        s += g_part[(slice * per + b) * MFEAT + col];
    red[slice][col] = s;
    __syncthreads();
    if (slice == 0)
        g_ksum[col] = red[0][col] + red[1][col] + red[2][col] + red[3][col];
}

extern "C" void kernel_launch(void* const* d_in, const int* in_sizes, int n_in,
                              void* d_out, int out_size)
{
    const float* Q     = (const float*)d_in[0];
    const float* K     = (const float*)d_in[1];
    const float* V     = (const float*)d_in[2];
    const float* omega = (const float*)d_in[3];
    float* out = (float*)d_out;

    cudaFuncSetAttribute(gemm_kernel<true>,
                         cudaFuncAttributeMaxDynamicSharedMemorySize, SMEM_BYTES);
    cudaFuncSetAttribute(gemm_kernel<false>,
                         cudaFuncAttributeMaxDynamicSharedMemorySize, SMEM_BYTES);

    init_kernel<<<1, 1>>>();
    gemm_kernel<true ><<<GEMM_BLOCKS, GEMM_THREADS, SMEM_BYTES>>>(K, omega, nullptr, nullptr);
    kp_kernel<<<KP_BLOCKS, MFEAT>>>();
    ksum_kernel<<<1, 1024>>>();
    gemm_kernel<false><<<GEMM_BLOCKS, GEMM_THREADS, SMEM_BYTES>>>(Q, omega, V, out);
}

// round 16
// speedup vs baseline: 3.2169x; 3.2169x over previous
#include <cuda_runtime.h>
#include <cuda_bf16.h>
#include <cuda_fp16.h>
#include <math_constants.h>

typedef unsigned u32; typedef unsigned long long u64;

#define NROWS 262144
#define DIMQ  128
#define MFEAT 256
#define SCALE 0.29730177875068026f   // 128^-0.25
#define ISM 0.0625f                  // 1/sqrt(256)
#define PHI_EPS 1e-4f
#define EPSISM (PHI_EPS * ISM)

#define TILE_ROWS 128
#define NCTA (NROWS / TILE_ROWS)     // 2048
#define THREADS 256
#define PADB 272                     // bytes per k-row: 136 bf16 (128 data + 8 pad)

// smem layout (bytes)
#define SB_HI 0                      // omega^T hi  [256][PADB]
#define SB_LO 69632                  // omega^T lo
#define SA_HI 139264                 // X tile hi   [128][PADB]
#define SA_LO 174080                 // X tile lo
#define MISC  208896
#define OFF_H    (MISC + 0)          // 128 f  (pass1 h_K)
#define OFF_KS   (MISC + 512)        // 256 f
#define OFF_MAXR (MISC + 1536)       // 128*4 f rowmax (pass1: colsum part[256][2])
#define OFF_W    (MISC + 3584)       // 128*4 f
#define OFF_N    (MISC + 5632)       // 128*4 f
#define OFF_SC   (MISC + 7680)       // 128 f
#define OFF_WMAX (MISC + 8192)       // 8 f
#define SMEM_TOTAL (MISC + 8448)     // 217344 B

// device globals (allocation-free scratch)
__device__ unsigned char g_Bimg[2 * 69632];          // padded omega^T hi|lo
__device__ uint2 g_kp[(size_t)NCTA * 8 * 32 * 32];   // Kp fp16x4 in fragment order (128MB)
__device__ float g_part[NCTA * MFEAT];
__device__ float g_part2[64 * MFEAT];
__device__ float g_lmax[NCTA];
__device__ float g_ksum[MFEAT];
__device__ unsigned g_kmax_bits;

// monotonic float<->uint encoding (deterministic atomicMax)
__device__ __forceinline__ unsigned fenc(float f) {
    unsigned u = __float_as_uint(f);
    return (u >> 31) ? ~u : (u | 0x80000000u);
}
__device__ __forceinline__ float fdec(unsigned u) {
    return (u >> 31) ? __uint_as_float(u & 0x7fffffffu) : __uint_as_float(~u);
}

// mma.sync m16n8k16 bf16 (baseline PTX ISA — no sm_103a feature needed)
#define MMA(c, a, b)                                                            \
    asm volatile("mma.sync.aligned.m16n8k16.row.col.f32.bf16.bf16.f32 "         \
        "{%0,%1,%2,%3}, {%4,%5,%6,%7}, {%8,%9}, {%0,%1,%2,%3};"                 \
        : "+f"((c)[0]), "+f"((c)[1]), "+f"((c)[2]), "+f"((c)[3])                \
        : "r"((a)[0]), "r"((a)[1]), "r"((a)[2]), "r"((a)[3]),                   \
          "r"((b)[0]), "r"((b)[1]))

// pack two f32 -> f16x2 (lo=e0, hi=e1)
__device__ __forceinline__ u32 pack_h2(float e0, float e1) {
    u32 p;
    asm("cvt.rn.f16x2.f32 %0, %1, %2;" : "=r"(p) : "f"(e1), "f"(e0));
    return p;
}

__global__ void init_kernel() { g_kmax_bits = 0u; }

// omega [128][256] -> transposed, bf16 hi/lo split, padded image
__global__ __launch_bounds__(256)
void prep_b_kernel(const float* __restrict__ omega) {
    int idx = blockIdx.x * 256 + threadIdx.x;     // 0..32767
    int n = idx >> 7, k = idx & 127;
    float v = omega[k * MFEAT + n];
    __nv_bfloat16 hi = __float2bfloat16_rn(v);
    __nv_bfloat16 lo = __float2bfloat16_rn(v - __bfloat162float(hi));
    *(__nv_bfloat16*)(g_Bimg + n * PADB + k * 2) = hi;
    *(__nv_bfloat16*)(g_Bimg + SB_LO + n * PADB + k * 2) = lo;
}

// convert float4 of X (row f>>5, cols (f&31)*4) -> bf16 hi/lo padded smem (+h)
template <bool WANT_H>
__device__ __forceinline__ void cvt_store(char* smem, int f, float4 v) {
    const int row = f >> 5, lane = f & 31;
    float x0 = v.x * SCALE, x1 = v.y * SCALE, x2 = v.z * SCALE, x3 = v.w * SCALE;
    if (WANT_H) {
        float s = x0 * x0 + x1 * x1 + x2 * x2 + x3 * x3;
        #pragma unroll
        for (int o = 16; o > 0; o >>= 1) s += __shfl_xor_sync(0xffffffffu, s, o);
        if (lane == 0) ((float*)(smem + OFF_H))[row] = 0.5f * s;
    }
    __nv_bfloat16 h0 = __float2bfloat16_rn(x0), h1 = __float2bfloat16_rn(x1);
    __nv_bfloat16 h2 = __float2bfloat16_rn(x2), h3 = __float2bfloat16_rn(x3);
    __nv_bfloat16 l0 = __float2bfloat16_rn(x0 - __bfloat162float(h0));
    __nv_bfloat16 l1 = __float2bfloat16_rn(x1 - __bfloat162float(h1));
    __nv_bfloat16 l2 = __float2bfloat16_rn(x2 - __bfloat162float(h2));
    __nv_bfloat16 l3 = __float2bfloat16_rn(x3 - __bfloat162float(h3));
    uint2 hv, lv;
    hv.x = ((u32)__bfloat16_as_ushort(h1) << 16) | __bfloat16_as_ushort(h0);
    hv.y = ((u32)__bfloat16_as_ushort(h3) << 16) | __bfloat16_as_ushort(h2);
    lv.x = ((u32)__bfloat16_as_ushort(l1) << 16) | __bfloat16_as_ushort(l0);
    lv.y = ((u32)__bfloat16_as_ushort(l3) << 16) | __bfloat16_as_ushort(l2);
    const u32 off = (u32)row * PADB + (u32)lane * 8;
    *(uint2*)(smem + SA_HI + off) = hv;
    *(uint2*)(smem + SA_LO + off) = lv;
}

// warp GEMM: acc[mf][nf][c] += (Xhi+Xlo)·(Whi+Wlo) minus lo·lo  (3 products)
__device__ __forceinline__ void do_gemm(float (&acc)[4][8][4], const char* smem,
                                        int lane, int wm, int wn)
{
    const int g = lane >> 2, t = lane & 3;
    const int rbase = wm * 64 + g;
    const int nbase = wn * 64 + g;
    #pragma unroll
    for (int ks = 0; ks < 8; ks++) {
        const int k0 = ks * 16 + t * 2;
        u32 Ah[4][4], Al[4][4], Bh[8][2], Bl[8][2];
        #pragma unroll
        for (int mf = 0; mf < 4; mf++) {
            u32 o = (u32)(rbase + mf * 16) * PADB + (u32)k0 * 2;
            Ah[mf][0] = *(const u32*)(smem + SA_HI + o);
            Ah[mf][1] = *(const u32*)(smem + SA_HI + o + 8 * PADB);
            Ah[mf][2] = *(const u32*)(smem + SA_HI + o + 16);
            Ah[mf][3] = *(const u32*)(smem + SA_HI + o + 8 * PADB + 16);
            Al[mf][0] = *(const u32*)(smem + SA_LO + o);
            Al[mf][1] = *(const u32*)(smem + SA_LO + o + 8 * PADB);
            Al[mf][2] = *(const u32*)(smem + SA_LO + o + 16);
            Al[mf][3] = *(const u32*)(smem + SA_LO + o + 8 * PADB + 16);
        }
        #pragma unroll
        for (int nf = 0; nf < 8; nf++) {
            u32 o = (u32)(nbase + nf * 8) * PADB + (u32)k0 * 2;
            Bh[nf][0] = *(const u32*)(smem + SB_HI + o);
            Bh[nf][1] = *(const u32*)(smem + SB_HI + o + 16);
            Bl[nf][0] = *(const u32*)(smem + SB_LO + o);
            Bl[nf][1] = *(const u32*)(smem + SB_LO + o + 16);
        }
        #pragma unroll
        for (int mf = 0; mf < 4; mf++)
            #pragma unroll
            for (int nf = 0; nf < 8; nf++) {
                MMA(acc[mf][nf], Ah[mf], Bh[nf]);
                MMA(acc[mf][nf], Ah[mf], Bl[nf]);
                MMA(acc[mf][nf], Al[mf], Bh[nf]);
            }
    }
}

__device__ __forceinline__ void load_b_image(char* smem, int tid) {
    const float4* src = (const float4*)g_Bimg;
    float4* dst = (float4*)smem;
    #pragma unroll
    for (int q = 0; q < 34; q++) dst[tid + q * 256] = src[tid + q * 256];  // 8704 f4
}

// ---------------------------------------------------------------------------
// pass1: K-GEMM; raw-max -> atomicMax; exp(U-h-Lmax) -> g_kp (fp16, fragment
// order) + fixed-order column sums -> g_part. Deterministic.
// ---------------------------------------------------------------------------
__global__ __launch_bounds__(THREADS, 1)
void pass1_kernel(const float* __restrict__ Kin)
{
    extern __shared__ __align__(16) char smem[];
    const int tid = threadIdx.x, lane = tid & 31, w = tid >> 5;
    const int wm = w & 1, wn = w >> 1;
    const int g = lane >> 2, t = lane & 3;
    const size_t row0 = (size_t)blockIdx.x * TILE_ROWS;

    load_b_image(smem, tid);
    {
        const float4* Xg = (const float4*)(Kin + row0 * DIMQ);
        #pragma unroll
        for (int q = 0; q < 16; q++) {
            int f = tid + q * 256;
            cvt_store<true>(smem, f, Xg[f]);
        }
    }
    __syncthreads();

    float acc[4][8][4];
    #pragma unroll
    for (int a = 0; a < 4; a++)
        #pragma unroll
        for (int b = 0; b < 8; b++)
            #pragma unroll
            for (int c = 0; c < 4; c++) acc[a][b][c] = 0.f;

    do_gemm(acc, smem, lane, wm, wn);

    // CTA-local raw max
    float mx = -CUDART_INF_F;
    #pragma unroll
    for (int a = 0; a < 4; a++)
        #pragma unroll
        for (int b = 0; b < 8; b++)
            #pragma unroll
            for (int c = 0; c < 4; c++) mx = fmaxf(mx, acc[a][b][c]);
    #pragma unroll
    for (int o = 16; o > 0; o >>= 1) mx = fmaxf(mx, __shfl_xor_sync(0xffffffffu, mx, o));
    if (lane == 0) ((float*)(smem + OFF_WMAX))[w] = mx;
    __syncthreads();
    if (tid == 0) {
        float L = ((float*)(smem + OFF_WMAX))[0];
        #pragma unroll
        for (int i = 1; i < 8; i++) L = fmaxf(L, ((float*)(smem + OFF_WMAX))[i]);
        atomicMax(&g_kmax_bits, fenc(L));
        g_lmax[blockIdx.x] = L;
        ((float*)(smem + OFF_SC))[0] = L;
    }
    __syncthreads();
    const float Lmax = ((float*)(smem + OFF_SC))[0];

    // exp + store fp16 + column partial sums
    float* part = (float*)(smem + OFF_MAXR);   // [256][2]
    const float* hbuf = (const float*)(smem + OFF_H);
    const size_t base = (((size_t)blockIdx.x * 8 + w) * 32) * 32 + lane;

    #pragma unroll
    for (int mf = 0; mf < 4; mf++) {
        const float hA = hbuf[wm * 64 + mf * 16 + g];
        const float hB = hbuf[wm * 64 + mf * 16 + g + 8];
        #pragma unroll
        for (int nf = 0; nf < 8; nf++) {
            float e0 = __expf(acc[mf][nf][0] - hA - Lmax);
            float e1 = __expf(acc[mf][nf][1] - hA - Lmax);
            float e2 = __expf(acc[mf][nf][2] - hB - Lmax);
            float e3 = __expf(acc[mf][nf][3] - hB - Lmax);
            acc[mf][nf][0] = e0; acc[mf][nf][1] = e1;
            acc[mf][nf][2] = e2; acc[mf][nf][3] = e3;
            uint2 val;
            val.x = pack_h2(e0, e1);
            val.y = pack_h2(e2, e3);
            g_kp[base + (size_t)(mf * 8 + nf) * 32] = val;
        }
    }
    #pragma unroll
    for (int nf = 0; nf < 8; nf++) {
        float s0 = 0.f, s1 = 0.f;
        #pragma unroll
        for (int mf = 0; mf < 4; mf++) {
            s0 += acc[mf][nf][0] + acc[mf][nf][2];
            s1 += acc[mf][nf][1] + acc[mf][nf][3];
        }
        #pragma unroll
        for (int o = 4; o < 32; o <<= 1) {
            s0 += __shfl_xor_sync(0xffffffffu, s0, o);
            s1 += __shfl_xor_sync(0xffffffffu, s1, o);
        }
        if (g == 0) {
            int col = wn * 64 + nf * 8 + t * 2;
            part[col * 2 + wm] = s0;
            part[(col + 1) * 2 + wm] = s1;
        }
    }
    __syncthreads();
    g_part[blockIdx.x * MFEAT + tid] = part[tid * 2] + part[tid * 2 + 1];
}

// two-stage fixed-order combine (deterministic)
__global__ __launch_bounds__(256)
void combine1_kernel()
{
    const float gmax = fdec(g_kmax_bits);
    const int b0 = blockIdx.x * 32, c = threadIdx.x;
    float acc = 0.f;
    #pragma unroll 4
    for (int i = 0; i < 32; i++)
        acc = fmaf(g_part[(b0 + i) * MFEAT + c], __expf(g_lmax[b0 + i] - gmax), acc);
    g_part2[blockIdx.x * MFEAT + c] = acc;
}
__global__ __launch_bounds__(256)
void combine2_kernel()
{
    const int c = threadIdx.x;
    float acc = 0.f;
    #pragma unroll 8
    for (int b = 0; b < 64; b++) acc += g_part2[b * MFEAT + c];
    g_ksum[c] = (acc + (float)NROWS * PHI_EPS) * ISM;
}

// ---------------------------------------------------------------------------
// pass2: Q-GEMM (h cancels) + fused epilogue reading Kp fragments back.
// ---------------------------------------------------------------------------
__global__ __launch_bounds__(THREADS, 1)
void pass2_kernel(const float* __restrict__ Qin, const float* __restrict__ V,
                  float* __restrict__ out)
{
    extern __shared__ __align__(16) char smem[];
    const int tid = threadIdx.x, lane = tid & 31, w = tid >> 5;
    const int wm = w & 1, wn = w >> 1;
    const int g = lane >> 2, t = lane & 3;
    const size_t row0 = (size_t)blockIdx.x * TILE_ROWS;

    ((float*)(smem + OFF_KS))[tid] = g_ksum[tid];
    const float gmax = fdec(g_kmax_bits);
    const float sc_cta = __expf(g_lmax[blockIdx.x] - gmax) * ISM;

    load_b_image(smem, tid);
    {
        const float4* Xg = (const float4*)(Qin + row0 * DIMQ);
        #pragma unroll
        for (int q = 0; q < 16; q++) {
            int f = tid + q * 256;
            cvt_store<false>(smem, f, Xg[f]);
        }
    }
    __syncthreads();

    float acc[4][8][4];
    #pragma unroll
    for (int a = 0; a < 4; a++)
        #pragma unroll
        for (int b = 0; b < 8; b++)
            #pragma unroll
            for (int c = 0; c < 4; c++) acc[a][b][c] = 0.f;

    do_gemm(acc, smem, lane, wm, wn);

    // per-row max of raw U_Q (h cancels in qp)
    float* sMaxR = (float*)(smem + OFF_MAXR);   // [128][4]
    #pragma unroll
    for (int mf = 0; mf < 4; mf++) {
        float mA = -CUDART_INF_F, mB = -CUDART_INF_F;
        #pragma unroll
        for (int nf = 0; nf < 8; nf++) {
            mA = fmaxf(mA, fmaxf(acc[mf][nf][0], acc[mf][nf][1]));
            mB = fmaxf(mB, fmaxf(acc[mf][nf][2], acc[mf][nf][3]));
        }
        mA = fmaxf(mA, __shfl_xor_sync(0xffffffffu, mA, 1));
        mA = fmaxf(mA, __shfl_xor_sync(0xffffffffu, mA, 2));
        mB = fmaxf(mB, __shfl_xor_sync(0xffffffffu, mB, 1));
        mB = fmaxf(mB, __shfl_xor_sync(0xffffffffu, mB, 2));
        if (t == 0) {
            sMaxR[(wm * 64 + mf * 16 + g) * 4 + wn] = mA;
            sMaxR[(wm * 64 + mf * 16 + g + 8) * 4 + wn] = mB;
        }
    }
    __syncthreads();

    float* sW = (float*)(smem + OFF_W);
    float* sN = (float*)(smem + OFF_N);
    const float* sKS = (const float*)(smem + OFF_KS);
    const size_t base = (((size_t)blockIdx.x * 8 + w) * 32) * 32 + lane;

    #pragma unroll
    for (int mf = 0; mf < 4; mf++) {
        const int rA = wm * 64 + mf * 16 + g, rB = rA + 8;
        float4 m4 = ((const float4*)sMaxR)[rA];
        const float mA = fmaxf(fmaxf(m4.x, m4.y), fmaxf(m4.z, m4.w));
        m4 = ((const float4*)sMaxR)[rB];
        const float mB = fmaxf(fmaxf(m4.x, m4.y), fmaxf(m4.z, m4.w));

        float wvA = 0.f, nrA = 0.f, wvB = 0.f, nrB = 0.f;
        #pragma unroll
        for (int nf = 0; nf < 8; nf++) {
            const int col = wn * 64 + nf * 8 + t * 2;
            const float ks0 = sKS[col], ks1 = sKS[col + 1];
            uint2 kv = g_kp[base + (size_t)(mf * 8 + nf) * 32];
            __half2 h01 = *reinterpret_cast<__half2*>(&kv.x);
            __half2 h23 = *reinterpret_cast<__half2*>(&kv.y);
            float2 k01 = __half22float2(h01);
            float2 k23 = __half22float2(h23);

            float qp0 = fmaf(__expf(acc[mf][nf][0] - mA), ISM, EPSISM);
            float qp1 = fmaf(__expf(acc[mf][nf][1] - mA), ISM, EPSISM);
            float qp2 = fmaf(__expf(acc[mf][nf][2] - mB), ISM, EPSISM);
            float qp3 = fmaf(__expf(acc[mf][nf][3] - mB), ISM, EPSISM);
            float kp0 = fmaf(k01.x, sc_cta, EPSISM);
            float kp1 = fmaf(k01.y, sc_cta, EPSISM);
            float kp2 = fmaf(k23.x, sc_cta, EPSISM);
            float kp3 = fmaf(k23.y, sc_cta, EPSISM);

            wvA = fmaf(qp0, kp0, fmaf(qp1, kp1, wvA));
            nrA = fmaf(qp0, ks0, fmaf(qp1, ks1, nrA));
            wvB = fmaf(qp2, kp2, fmaf(qp3, kp3, wvB));
            nrB = fmaf(qp2, ks0, fmaf(qp3, ks1, nrB));
        }
        wvA += __shfl_xor_sync(0xffffffffu, wvA, 1);
        wvA += __shfl_xor_sync(0xffffffffu, wvA, 2);
        nrA += __shfl_xor_sync(0xffffffffu, nrA, 1);
        nrA += __shfl_xor_sync(0xffffffffu, nrA, 2);
        wvB += __shfl_xor_sync(0xffffffffu, wvB, 1);
        wvB += __shfl_xor_sync(0xffffffffu, wvB, 2);
        nrB += __shfl_xor_sync(0xffffffffu, nrB, 1);
        nrB += __shfl_xor_sync(0xffffffffu, nrB, 2);
        if (t == 0) {
            sW[rA * 4 + wn] = wvA; sN[rA * 4 + wn] = nrA;
            sW[rB * 4 + wn] = wvB; sN[rB * 4 + wn] = nrB;
        }
    }
    __syncthreads();
    if (tid < 128) {
        float4 w4 = ((const float4*)sW)[tid];
        float4 n4 = ((const float4*)sN)[tid];
        ((float*)(smem + OFF_SC))[tid] =
            (w4.x + w4.y + w4.z + w4.w) / ((n4.x + n4.y + n4.z + n4.w) + 1e-8f);
    }
    __syncthreads();

    {
        const float4* Vg = (const float4*)(V + row0 * DIMQ);
        float4* Og = (float4*)(out + row0 * DIMQ);
        const float* sc = (const float*)(smem + OFF_SC);
        #pragma unroll
        for (int q = 0; q < 16; q++) {
            int f = tid + q * 256;
            float4 v = Vg[f];
            float s = sc[f >> 5];
            v.x *= s; v.y *= s; v.z *= s; v.w *= s;
            Og[f] = v;
        }
    }
}

extern "C" void kernel_launch(void* const* d_in, const int* in_sizes, int n_in,
                              void* d_out, int out_size)
{
    const float* Q     = (const float*)d_in[0];
    const float* K     = (const float*)d_in[1];
    const float* V     = (const float*)d_in[2];
    const float* omega = (const float*)d_in[3];
    float* out = (float*)d_out;

    cudaFuncSetAttribute(pass1_kernel,
                         cudaFuncAttributeMaxDynamicSharedMemorySize, SMEM_TOTAL);
    cudaFuncSetAttribute(pass2_kernel,
                         cudaFuncAttributeMaxDynamicSharedMemorySize, SMEM_TOTAL);

    init_kernel<<<1, 1>>>();
    prep_b_kernel<<<128, 256>>>(omega);
    pass1_kernel<<<NCTA, THREADS, SMEM_TOTAL>>>(K);
    combine1_kernel<<<64, 256>>>();
    combine2_kernel<<<1, 256>>>();
    pass2_kernel<<<NCTA, THREADS, SMEM_TOTAL>>>(Q, V, out);
}

// round 17
// speedup vs baseline: 3.3165x; 1.0310x over previous
#include <cuda_runtime.h>
#include <cuda_bf16.h>
#include <cuda_fp16.h>
#include <math_constants.h>

typedef unsigned u32; typedef unsigned long long u64;

#define NROWS 262144
#define DIMQ  128
#define MFEAT 256
#define SCALE 0.29730177875068026f   // 128^-0.25
#define ISM 0.0625f                  // 1/sqrt(256)
#define PHI_EPS 1e-4f
#define EPSISM (PHI_EPS * ISM)

#define TILE_ROWS 128
#define NCTA (NROWS / TILE_ROWS)     // 2048
#define THREADS 512
#define PADB 272                     // bytes per k-row: 136 bf16 (128 data + 8 pad)

// smem layout (bytes)
#define SB_HI 0                      // omega^T hi  [256][PADB]
#define SB_LO 69632                  // omega^T lo
#define SA_HI 139264                 // X tile hi   [128][PADB]
#define SA_LO 174080                 // X tile lo
#define MISC  208896
#define OFF_H    (MISC + 0)          // 128 f
#define OFF_KS   (MISC + 512)        // 256 f
#define OFF_PART (MISC + 1536)       // 256*4 f (pass1 colsums / pass2 rowmax[128][4])
#define OFF_W    (MISC + 5632)       // 128*4 f
#define OFF_N    (MISC + 7680)       // 128*4 f
#define OFF_SC   (MISC + 9728)       // 128 f
#define OFF_WMAX (MISC + 10240)      // 16 f
#define SMEM_TOTAL (MISC + 10304)    // 219200 B

// device globals (allocation-free scratch)
__device__ unsigned char g_Bimg[2 * 69632];            // padded omega^T hi|lo
__device__ uint2 g_kp[(size_t)NCTA * 16 * 16 * 32];    // Kp fp16x4, fragment order
__device__ float g_part[NCTA * MFEAT];
__device__ float g_part2[128 * MFEAT];
__device__ float g_lmax[NCTA];
__device__ float g_ksum[MFEAT];
__device__ unsigned g_kmax_bits;

__device__ __forceinline__ unsigned fenc(float f) {
    unsigned u = __float_as_uint(f);
    return (u >> 31) ? ~u : (u | 0x80000000u);
}
__device__ __forceinline__ float fdec(unsigned u) {
    return (u >> 31) ? __uint_as_float(u & 0x7fffffffu) : __uint_as_float(~u);
}
__device__ __forceinline__ u32 smem_u32(const void* p) {
    u32 a;
    asm("{ .reg .u64 t; cvta.to.shared.u64 t, %1; cvt.u32.u64 %0, t; }" : "=r"(a) : "l"(p));
    return a;
}

#define MMA(c, a, b)                                                            \
    asm volatile("mma.sync.aligned.m16n8k16.row.col.f32.bf16.bf16.f32 "         \
        "{%0,%1,%2,%3}, {%4,%5,%6,%7}, {%8,%9}, {%0,%1,%2,%3};"                 \
        : "+f"((c)[0]), "+f"((c)[1]), "+f"((c)[2]), "+f"((c)[3])                \
        : "r"((a)[0]), "r"((a)[1]), "r"((a)[2]), "r"((a)[3]),                   \
          "r"((b)[0]), "r"((b)[1]))

#define LDSM_X4(r, addr)                                                        \
    asm volatile("ldmatrix.sync.aligned.m8n8.x4.shared.b16 {%0,%1,%2,%3}, [%4];"\
        : "=r"((r)[0]), "=r"((r)[1]), "=r"((r)[2]), "=r"((r)[3]) : "r"(addr))

__device__ __forceinline__ u32 pack_h2(float e0, float e1) {
    u32 p;
    asm("cvt.rn.f16x2.f32 %0, %1, %2;" : "=r"(p) : "f"(e1), "f"(e0));
    return p;
}

__global__ void init_kernel() { g_kmax_bits = 0u; }

// omega [128][256] -> transposed, bf16 hi/lo split, padded image
__global__ __launch_bounds__(256)
void prep_b_kernel(const float* __restrict__ omega) {
    int idx = blockIdx.x * 256 + threadIdx.x;     // 0..32767
    int n = idx >> 7, k = idx & 127;
    float v = omega[k * MFEAT + n];
    __nv_bfloat16 hi = __float2bfloat16_rn(v);
    __nv_bfloat16 lo = __float2bfloat16_rn(v - __bfloat162float(hi));
    *(__nv_bfloat16*)(g_Bimg + n * PADB + k * 2) = hi;
    *(__nv_bfloat16*)(g_Bimg + SB_LO + n * PADB + k * 2) = lo;
}

// convert float4 of X (row f>>5, cols (f&31)*4) -> bf16 hi/lo padded smem (+h)
template <bool WANT_H>
__device__ __forceinline__ void cvt_store(char* smem, int f, float4 v) {
    const int row = f >> 5, lane = f & 31;
    float x0 = v.x * SCALE, x1 = v.y * SCALE, x2 = v.z * SCALE, x3 = v.w * SCALE;
    if (WANT_H) {
        float s = x0 * x0 + x1 * x1 + x2 * x2 + x3 * x3;
        #pragma unroll
        for (int o = 16; o > 0; o >>= 1) s += __shfl_xor_sync(0xffffffffu, s, o);
        if (lane == 0) ((float*)(smem + OFF_H))[row] = 0.5f * s;
    }
    __nv_bfloat16 h0 = __float2bfloat16_rn(x0), h1 = __float2bfloat16_rn(x1);
    __nv_bfloat16 h2 = __float2bfloat16_rn(x2), h3 = __float2bfloat16_rn(x3);
    __nv_bfloat16 l0 = __float2bfloat16_rn(x0 - __bfloat162float(h0));
    __nv_bfloat16 l1 = __float2bfloat16_rn(x1 - __bfloat162float(h1));
    __nv_bfloat16 l2 = __float2bfloat16_rn(x2 - __bfloat162float(h2));
    __nv_bfloat16 l3 = __float2bfloat16_rn(x3 - __bfloat162float(h3));
    uint2 hv, lv;
    hv.x = ((u32)__bfloat16_as_ushort(h1) << 16) | __bfloat16_as_ushort(h0);
    hv.y = ((u32)__bfloat16_as_ushort(h3) << 16) | __bfloat16_as_ushort(h2);
    lv.x = ((u32)__bfloat16_as_ushort(l1) << 16) | __bfloat16_as_ushort(l0);
    lv.y = ((u32)__bfloat16_as_ushort(l3) << 16) | __bfloat16_as_ushort(l2);
    const u32 off = (u32)row * PADB + (u32)lane * 8;
    *(uint2*)(smem + SA_HI + off) = hv;
    *(uint2*)(smem + SA_LO + off) = lv;
}

__device__ __forceinline__ void load_b_image(char* smem, int tid) {
    const float4* src = (const float4*)g_Bimg;
    float4* dst = (float4*)smem;
    #pragma unroll
    for (int q = 0; q < 17; q++) dst[tid + q * THREADS] = src[tid + q * THREADS];
}

// warp GEMM via ldmatrix: acc[mf][nf] += Ahi·Bhi + Ahi·Blo + Alo·Bhi
// warp tile 32x64: wm in 0..3 (M strips of 32), wn in 0..3 (N strips of 64)
__device__ __forceinline__ void do_gemm(float (&acc)[2][8][4], u32 sb,
                                        int lane, int wm, int wn)
{
    const int sub = lane >> 3;
    const u32 aRow = (u32)(wm * 32 + (sub & 1) * 8 + (lane & 7));
    const u32 aK   = (u32)((sub >> 1) * 16);                 // bytes
    const u32 aH = sb + SA_HI + aRow * PADB + aK;
    const u32 aL = sb + SA_LO + aRow * PADB + aK;
    const u32 bRow = (u32)(wn * 64 + (sub >> 1) * 8 + (lane & 7));
    const u32 bK   = (u32)((sub & 1) * 16);                  // bytes
    const u32 bH = sb + SB_HI + bRow * PADB + bK;
    const u32 bL = sb + SB_LO + bRow * PADB + bK;

    #pragma unroll
    for (int ks = 0; ks < 8; ks++) {
        const u32 kb = (u32)ks * 32;
        u32 Ah[2][4], Al[2][4];
        LDSM_X4(Ah[0], aH + kb);
        LDSM_X4(Ah[1], aH + 16 * PADB + kb);
        LDSM_X4(Al[0], aL + kb);
        LDSM_X4(Al[1], aL + 16 * PADB + kb);
        #pragma unroll
        for (int j = 0; j < 4; j++) {
            u32 Bh[4], Bl[4];
            LDSM_X4(Bh, bH + (u32)j * 16 * PADB + kb);
            LDSM_X4(Bl, bL + (u32)j * 16 * PADB + kb);
            #pragma unroll
            for (int mf = 0; mf < 2; mf++) {
                MMA(acc[mf][2 * j],     Ah[mf], Bh);
                MMA(acc[mf][2 * j],     Ah[mf], Bl);
                MMA(acc[mf][2 * j],     Al[mf], Bh);
                MMA(acc[mf][2 * j + 1], Ah[mf], Bh + 2);
                MMA(acc[mf][2 * j + 1], Ah[mf], Bl + 2);
                MMA(acc[mf][2 * j + 1], Al[mf], Bh + 2);
            }
        }
    }
}

// ---------------------------------------------------------------------------
// pass1: K-GEMM; raw-max -> atomicMax; exp(U-h-Lmax) -> g_kp (fp16, fragment
// order) + fixed-order column sums. Deterministic.
// ---------------------------------------------------------------------------
__global__ __launch_bounds__(THREADS, 1)
void pass1_kernel(const float* __restrict__ Kin)
{
    extern __shared__ __align__(16) char smem[];
    const u32 sb = smem_u32(smem);
    const int tid = threadIdx.x, lane = tid & 31, w = tid >> 5;
    const int wm = w & 3, wn = w >> 2;
    const int g = lane >> 2, t = lane & 3;
    const size_t row0 = (size_t)blockIdx.x * TILE_ROWS;

    load_b_image(smem, tid);
    {
        const float4* Xg = (const float4*)(Kin + row0 * DIMQ);
        #pragma unroll
        for (int q = 0; q < 8; q++) {
            int f = tid + q * THREADS;
            cvt_store<true>(smem, f, Xg[f]);
        }
    }
    __syncthreads();

    float acc[2][8][4];
    #pragma unroll
    for (int a = 0; a < 2; a++)
        #pragma unroll
        for (int b = 0; b < 8; b++)
            #pragma unroll
            for (int c = 0; c < 4; c++) acc[a][b][c] = 0.f;

    do_gemm(acc, sb, lane, wm, wn);

    // CTA-local raw max
    float mx = -CUDART_INF_F;
    #pragma unroll
    for (int a = 0; a < 2; a++)
        #pragma unroll
        for (int b = 0; b < 8; b++)
            #pragma unroll
            for (int c = 0; c < 4; c++) mx = fmaxf(mx, acc[a][b][c]);
    #pragma unroll
    for (int o = 16; o > 0; o >>= 1) mx = fmaxf(mx, __shfl_xor_sync(0xffffffffu, mx, o));
    if (lane == 0) ((float*)(smem + OFF_WMAX))[w] = mx;
    __syncthreads();
    if (tid == 0) {
        float L = ((float*)(smem + OFF_WMAX))[0];
        #pragma unroll
        for (int i = 1; i < 16; i++) L = fmaxf(L, ((float*)(smem + OFF_WMAX))[i]);
        atomicMax(&g_kmax_bits, fenc(L));
        g_lmax[blockIdx.x] = L;
        ((float*)(smem + OFF_SC))[0] = L;
    }
    __syncthreads();
    const float Lmax = ((float*)(smem + OFF_SC))[0];

    // exp + store fp16 + column partial sums
    float* part = (float*)(smem + OFF_PART);   // [256][4]
    const float* hbuf = (const float*)(smem + OFF_H);
    const size_t base = ((size_t)blockIdx.x * 16 + w) * 512 + lane;

    #pragma unroll
    for (int mf = 0; mf < 2; mf++) {
        const float hA = hbuf[wm * 32 + mf * 16 + g];
        const float hB = hbuf[wm * 32 + mf * 16 + g + 8];
        #pragma unroll
        for (int nf = 0; nf < 8; nf++) {
            float e0 = __expf(acc[mf][nf][0] - hA - Lmax);
            float e1 = __expf(acc[mf][nf][1] - hA - Lmax);
            float e2 = __expf(acc[mf][nf][2] - hB - Lmax);
            float e3 = __expf(acc[mf][nf][3] - hB - Lmax);
            acc[mf][nf][0] = e0; acc[mf][nf][1] = e1;
            acc[mf][nf][2] = e2; acc[mf][nf][3] = e3;
            uint2 val;
            val.x = pack_h2(e0, e1);
            val.y = pack_h2(e2, e3);
            g_kp[base + (size_t)(mf * 8 + nf) * 32] = val;
        }
    }
    #pragma unroll
    for (int nf = 0; nf < 8; nf++) {
        float s0 = 0.f, s1 = 0.f;
        #pragma unroll
        for (int mf = 0; mf < 2; mf++) {
            s0 += acc[mf][nf][0] + acc[mf][nf][2];
            s1 += acc[mf][nf][1] + acc[mf][nf][3];
        }
        #pragma unroll
        for (int o = 4; o < 32; o <<= 1) {
            s0 += __shfl_xor_sync(0xffffffffu, s0, o);
            s1 += __shfl_xor_sync(0xffffffffu, s1, o);
        }
        if (g == 0) {
            int col = wn * 64 + nf * 8 + t * 2;
            part[col * 4 + wm] = s0;
            part[(col + 1) * 4 + wm] = s1;
        }
    }
    __syncthreads();
    if (tid < MFEAT) {
        float4 p4 = ((const float4*)part)[tid];
        g_part[blockIdx.x * MFEAT + tid] = (p4.x + p4.y) + (p4.z + p4.w);
    }
}

// two-stage fixed-order combine (deterministic)
__global__ __launch_bounds__(256)
void combine1_kernel()
{
    const float gmax = fdec(g_kmax_bits);
    const int b0 = blockIdx.x * 16, c = threadIdx.x;
    float acc = 0.f;
    #pragma unroll 4
    for (int i = 0; i < 16; i++)
        acc = fmaf(g_part[(b0 + i) * MFEAT + c], __expf(g_lmax[b0 + i] - gmax), acc);
    g_part2[blockIdx.x * MFEAT + c] = acc;
}
__global__ __launch_bounds__(256)
void combine2_kernel()
{
    const int c = threadIdx.x;
    float acc = 0.f;
    #pragma unroll 8
    for (int b = 0; b < 128; b++) acc += g_part2[b * MFEAT + c];
    g_ksum[c] = (acc + (float)NROWS * PHI_EPS) * ISM;
}

// ---------------------------------------------------------------------------
// pass2: Q-GEMM (h cancels) + fused epilogue reading Kp fragments back.
// ---------------------------------------------------------------------------
__global__ __launch_bounds__(THREADS, 1)
void pass2_kernel(const float* __restrict__ Qin, const float* __restrict__ V,
                  float* __restrict__ out)
{
    extern __shared__ __align__(16) char smem[];
    const u32 sb = smem_u32(smem);
    const int tid = threadIdx.x, lane = tid & 31, w = tid >> 5;
    const int wm = w & 3, wn = w >> 2;
    const int g = lane >> 2, t = lane & 3;
    const size_t row0 = (size_t)blockIdx.x * TILE_ROWS;

    if (tid < MFEAT) ((float*)(smem + OFF_KS))[tid] = g_ksum[tid];
    const float gmax = fdec(g_kmax_bits);
    const float sc_cta = __expf(g_lmax[blockIdx.x] - gmax) * ISM;

    load_b_image(smem, tid);
    {
        const float4* Xg = (const float4*)(Qin + row0 * DIMQ);
        #pragma unroll
        for (int q = 0; q < 8; q++) {
            int f = tid + q * THREADS;
            cvt_store<false>(smem, f, Xg[f]);
        }
    }
    __syncthreads();

    float acc[2][8][4];
    #pragma unroll
    for (int a = 0; a < 2; a++)
        #pragma unroll
        for (int b = 0; b < 8; b++)
            #pragma unroll
            for (int c = 0; c < 4; c++) acc[a][b][c] = 0.f;

    do_gemm(acc, sb, lane, wm, wn);

    // per-row max of raw U_Q (h cancels in qp)
    float* sMaxR = (float*)(smem + OFF_PART);   // [128][4]
    #pragma unroll
    for (int mf = 0; mf < 2; mf++) {
        float mA = -CUDART_INF_F, mB = -CUDART_INF_F;
        #pragma unroll
        for (int nf = 0; nf < 8; nf++) {
            mA = fmaxf(mA, fmaxf(acc[mf][nf][0], acc[mf][nf][1]));
            mB = fmaxf(mB, fmaxf(acc[mf][nf][2], acc[mf][nf][3]));
        }
        mA = fmaxf(mA, __shfl_xor_sync(0xffffffffu, mA, 1));
        mA = fmaxf(mA, __shfl_xor_sync(0xffffffffu, mA, 2));
        mB = fmaxf(mB, __shfl_xor_sync(0xffffffffu, mB, 1));
        mB = fmaxf(mB, __shfl_xor_sync(0xffffffffu, mB, 2));
        if (t == 0) {
            sMaxR[(wm * 32 + mf * 16 + g) * 4 + wn] = mA;
            sMaxR[(wm * 32 + mf * 16 + g + 8) * 4 + wn] = mB;
        }
    }
    __syncthreads();

    float* sW = (float*)(smem + OFF_W);
    float* sN = (float*)(smem + OFF_N);
    const float* sKS = (const float*)(smem + OFF_KS);
    const size_t base = ((size_t)blockIdx.x * 16 + w) * 512 + lane;

    #pragma unroll
    for (int mf = 0; mf < 2; mf++) {
        const int rA = wm * 32 + mf * 16 + g, rB = rA + 8;
        float4 m4 = ((const float4*)sMaxR)[rA];
        const float mA = fmaxf(fmaxf(m4.x, m4.y), fmaxf(m4.z, m4.w));
        m4 = ((const float4*)sMaxR)[rB];
        const float mB = fmaxf(fmaxf(m4.x, m4.y), fmaxf(m4.z, m4.w));

        float wvA = 0.f, nrA = 0.f, wvB = 0.f, nrB = 0.f;
        #pragma unroll
        for (int nf = 0; nf < 8; nf++) {
            const int col = wn * 64 + nf * 8 + t * 2;
            const float ks0 = sKS[col], ks1 = sKS[col + 1];
            uint2 kv = g_kp[base + (size_t)(mf * 8 + nf) * 32];
            __half2 h01 = *reinterpret_cast<__half2*>(&kv.x);
            __half2 h23 = *reinterpret_cast<__half2*>(&kv.y);
            float2 k01 = __half22float2(h01);
            float2 k23 = __half22float2(h23);

            float qp0 = fmaf(__expf(acc[mf][nf][0] - mA), ISM, EPSISM);
            float qp1 = fmaf(__expf(acc[mf][nf][1] - mA), ISM, EPSISM);
            float qp2 = fmaf(__expf(acc[mf][nf][2] - mB), ISM, EPSISM);
            float qp3 = fmaf(__expf(acc[mf][nf][3] - mB), ISM, EPSISM);
            float kp0 = fmaf(k01.x, sc_cta, EPSISM);
            float kp1 = fmaf(k01.y, sc_cta, EPSISM);
            float kp2 = fmaf(k23.x, sc_cta, EPSISM);
            float kp3 = fmaf(k23.y, sc_cta, EPSISM);

            wvA = fmaf(qp0, kp0, fmaf(qp1, kp1, wvA));
            nrA = fmaf(qp0, ks0, fmaf(qp1, ks1, nrA));
            wvB = fmaf(qp2, kp2, fmaf(qp3, kp3, wvB));
            nrB = fmaf(qp2, ks0, fmaf(qp3, ks1, nrB));
        }
        wvA += __shfl_xor_sync(0xffffffffu, wvA, 1);
        wvA += __shfl_xor_sync(0xffffffffu, wvA, 2);
        nrA += __shfl_xor_sync(0xffffffffu, nrA, 1);
        nrA += __shfl_xor_sync(0xffffffffu, nrA, 2);
        wvB += __shfl_xor_sync(0xffffffffu, wvB, 1);
        wvB += __shfl_xor_sync(0xffffffffu, wvB, 2);
        nrB += __shfl_xor_sync(0xffffffffu, nrB, 1);
        nrB += __shfl_xor_sync(0xffffffffu, nrB, 2);
        if (t == 0) {
            sW[rA * 4 + wn] = wvA; sN[rA * 4 + wn] = nrA;
            sW[rB * 4 + wn] = wvB; sN[rB * 4 + wn] = nrB;
        }
    }
    __syncthreads();
    if (tid < 128) {
        float4 w4 = ((const float4*)sW)[tid];
        float4 n4 = ((const float4*)sN)[tid];
        ((float*)(smem + OFF_SC))[tid] =
            ((w4.x + w4.y) + (w4.z + w4.w)) / (((n4.x + n4.y) + (n4.z + n4.w)) + 1e-8f);
    }
    __syncthreads();

    {
        const float4* Vg = (const float4*)(V + row0 * DIMQ);
        float4* Og = (float4*)(out + row0 * DIMQ);
        const float* sc = (const float*)(smem + OFF_SC);
        #pragma unroll
        for (int q = 0; q < 8; q++) {
            int f = tid + q * THREADS;
            float4 v = Vg[f];
            float s = sc[f >> 5];
            v.x *= s; v.y *= s; v.z *= s; v.w *= s;
            Og[f] = v;
        }
    }
}

extern "C" void kernel_launch(void* const* d_in, const int* in_sizes, int n_in,
                              void* d_out, int out_size)
{
    const float* Q     = (const float*)d_in[0];
    const float* K     = (const float*)d_in[1];
    const float* V     = (const float*)d_in[2];
    const float* omega = (const float*)d_in[3];
    float* out = (float*)d_out;

    cudaFuncSetAttribute(pass1_kernel,
                         cudaFuncAttributeMaxDynamicSharedMemorySize, SMEM_TOTAL);
    cudaFuncSetAttribute(pass2_kernel,
                         cudaFuncAttributeMaxDynamicSharedMemorySize, SMEM_TOTAL);

    init_kernel<<<1, 1>>>();
    prep_b_kernel<<<128, 256>>>(omega);
    pass1_kernel<<<NCTA, THREADS, SMEM_TOTAL>>>(K);
    combine1_kernel<<<128, 256>>>();
    combine2_kernel<<<1, 256>>>();
    pass2_kernel<<<NCTA, THREADS, SMEM_TOTAL>>>(Q, V, out);
}